// round 4
// baseline (speedup 1.0000x reference)
#include <cuda_runtime.h>
#include <cuda_fp16.h>

#define N_NODES 50000
#define FEATS   64
#define N_EDGES 800000
#define NB      148          // blocks (<= SM count, 1 block/SM co-resident)
#define NT      512          // threads per block
#define NTHREADS (NB * NT)   // 75776
#define NWARPS   (NTHREADS / 32)
#define SCAN_CH  512
#define NCHUNK  ((N_NODES + SCAN_CH - 1) / SCAN_CH)   // 98
#define HST     68           // padded smem row stride (floats) = 17 float4
#define NTILE   ((N_NODES + 127) >> 7)                // 391 tiles of 128 nodes

// -------- device-global scratch (no allocation allowed) --------
__device__ int g_idx32;
__device__ int g_bar_count;
__device__ volatile int g_bar_gen;
__device__ int g_deg[N_NODES];
__device__ int g_rowptr[N_NODES + 1];
__device__ int g_blocksum[NCHUNK];
__device__ int g_blockoff[NCHUNK];
__device__ int g_fill[N_NODES];
__device__ int g_src32[N_EDGES];
__device__ int g_dst32[N_EDGES];
__device__ int g_col[N_EDGES];
__device__ __align__(16) __half2 g_xh [N_NODES * 32];   // fp16 gather table (embed)
__device__ __align__(16) __half2 g_h1h[N_NODES * 32];   // fp16 gather table (h1)
__device__ __align__(16) float g_h1[N_NODES * FEATS];
__device__ __align__(16) float g_h2[N_NODES * FEATS];

// -------- software grid barrier (monotonic generation counter) --------
__device__ __forceinline__ void grid_bar() {
    __syncthreads();
    if (threadIdx.x == 0) {
        __threadfence();
        int gen = g_bar_gen;
        if (atomicAdd(&g_bar_count, 1) == NB - 1) {
            g_bar_count = 0;
            __threadfence();
            g_bar_gen = gen + 1;
        } else {
            while (g_bar_gen == gen) { __nanosleep(32); }
        }
        __threadfence();
    }
    __syncthreads();
}

__device__ __forceinline__ int read_idx(const void* p, int i) {
    return g_idx32 ? ((const int*)p)[i] : (int)((const long long*)p)[i];
}

// -------- fused SAGE layer: per-tile smem aggregation + transform --------
// table: fp16 neighbor-gather source; Hself: fp32 self features
template <bool RELU>
__device__ void phase_layer(float* sm, const __half2* __restrict__ table,
                            const float* __restrict__ Hself,
                            const float* __restrict__ Ws, const float* __restrict__ Wn,
                            const float* __restrict__ bias,
                            float* __restrict__ C, __half2* __restrict__ Chalf) {
    float* sWs = sm;                 // 4096 floats
    float* sWn = sm + 4096;          // 4096 floats
    float* sH  = sm + 8192;          // 128 * HST
    float* sG  = sH + 128 * HST;     // 128 * HST

    int tid = threadIdx.x;
    int lane = tid & 31, wid = tid >> 5;
    int tx = tid & 15, ty = tid >> 4;

    #pragma unroll
    for (int i = 0; i < 2; i++) {
        int f = tid + i * NT;
        ((float4*)sWs)[f] = ((const float4*)Ws)[f];
        ((float4*)sWn)[f] = ((const float4*)Wn)[f];
    }
    float4 bv = ((const float4*)bias)[tx];

    for (int t = blockIdx.x; t < NTILE; t += NB) {
        int n0 = t << 7;
        __syncthreads();   // weights ready / previous tile fully consumed

        // self tile: 128 rows x 16 float4
        #pragma unroll
        for (int i = 0; i < 4; i++) {
            int f = tid + i * NT;
            int row = f >> 4, c = f & 15;
            int gr = n0 + row;
            float4 v = (gr < N_NODES) ? ((const float4*)Hself)[gr * 16 + c]
                                      : make_float4(0.f, 0.f, 0.f, 0.f);
            ((float4*)sH)[row * 17 + c] = v;
        }

        // aggregate: each warp owns 8 rows of the tile, gathers fp16 -> sG
        for (int r = 0; r < 8; r++) {
            int row = wid * 8 + r;
            int node = n0 + row;
            int s = 0, e = 0;
            if (node < N_NODES) { s = g_rowptr[node]; e = g_rowptr[node + 1]; }
            float2 a0 = make_float2(0.f, 0.f), a1 = make_float2(0.f, 0.f);
            float2 a2 = make_float2(0.f, 0.f), a3 = make_float2(0.f, 0.f);
            int j = s;
            for (; j + 3 < e; j += 4) {
                int c0 = g_col[j], c1 = g_col[j+1], c2 = g_col[j+2], c3 = g_col[j+3];
                float2 v0 = __half22float2(table[c0 * 32 + lane]);
                float2 v1 = __half22float2(table[c1 * 32 + lane]);
                float2 v2 = __half22float2(table[c2 * 32 + lane]);
                float2 v3 = __half22float2(table[c3 * 32 + lane]);
                a0.x += v0.x; a0.y += v0.y;
                a1.x += v1.x; a1.y += v1.y;
                a2.x += v2.x; a2.y += v2.y;
                a3.x += v3.x; a3.y += v3.y;
            }
            for (; j < e; j++) {
                float2 v = __half22float2(table[g_col[j] * 32 + lane]);
                a0.x += v.x; a0.y += v.y;
            }
            float inv = (e > s) ? (1.0f / (float)(e - s)) : 0.0f;
            float2 o;
            o.x = ((a0.x + a1.x) + (a2.x + a3.x)) * inv;
            o.y = ((a0.y + a1.y) + (a2.y + a3.y)) * inv;
            ((float2*)(sG + row * HST))[lane] = o;
        }
        __syncthreads();

        // transform: acc[node 4][out 4]
        float acc[4][4];
        #pragma unroll
        for (int i = 0; i < 4; i++) {
            acc[i][0] = bv.x; acc[i][1] = bv.y; acc[i][2] = bv.z; acc[i][3] = bv.w;
        }
        #pragma unroll 4
        for (int k = 0; k < 64; k++) {
            float4 ws = ((float4*)sWs)[k * 16 + tx];
            float4 wn = ((float4*)sWn)[k * 16 + tx];
            #pragma unroll
            for (int i = 0; i < 4; i++) {
                float hv = sH[(ty * 4 + i) * HST + k];
                acc[i][0] += hv * ws.x;
                acc[i][1] += hv * ws.y;
                acc[i][2] += hv * ws.z;
                acc[i][3] += hv * ws.w;
                float gv = sG[(ty * 4 + i) * HST + k];
                acc[i][0] += gv * wn.x;
                acc[i][1] += gv * wn.y;
                acc[i][2] += gv * wn.z;
                acc[i][3] += gv * wn.w;
            }
        }
        #pragma unroll
        for (int i = 0; i < 4; i++) {
            int row = n0 + ty * 4 + i;
            if (row < N_NODES) {
                float4 o;
                o.x = RELU ? fmaxf(acc[i][0], 0.f) : acc[i][0];
                o.y = RELU ? fmaxf(acc[i][1], 0.f) : acc[i][1];
                o.z = RELU ? fmaxf(acc[i][2], 0.f) : acc[i][2];
                o.w = RELU ? fmaxf(acc[i][3], 0.f) : acc[i][3];
                ((float4*)C)[row * 16 + tx] = o;
                if (Chalf) {
                    Chalf[row * 32 + tx * 2]     = __floats2half2_rn(o.x, o.y);
                    Chalf[row * 32 + tx * 2 + 1] = __floats2half2_rn(o.z, o.w);
                }
            }
        }
    }
}

// -------- final linear (no neighbor term) --------
__device__ void phase_final(float* sm, const float* __restrict__ H,
                            const float* __restrict__ W, const float* __restrict__ bias,
                            float* __restrict__ C) {
    float* sW = sm;
    float* sH = sm + 4096;
    int tid = threadIdx.x;
    int tx = tid & 15, ty = tid >> 4;
    #pragma unroll
    for (int i = 0; i < 2; i++) {
        int f = tid + i * NT;
        ((float4*)sW)[f] = ((const float4*)W)[f];
    }
    float4 bv = ((const float4*)bias)[tx];
    for (int t = blockIdx.x; t < NTILE; t += NB) {
        int n0 = t << 7;
        __syncthreads();
        #pragma unroll
        for (int i = 0; i < 4; i++) {
            int f = tid + i * NT;
            int row = f >> 4, c = f & 15;
            int gr = n0 + row;
            float4 v = (gr < N_NODES) ? ((const float4*)H)[gr * 16 + c]
                                      : make_float4(0.f, 0.f, 0.f, 0.f);
            ((float4*)sH)[row * 17 + c] = v;
        }
        __syncthreads();
        float acc[4][4];
        #pragma unroll
        for (int i = 0; i < 4; i++) {
            acc[i][0] = bv.x; acc[i][1] = bv.y; acc[i][2] = bv.z; acc[i][3] = bv.w;
        }
        #pragma unroll 8
        for (int k = 0; k < 64; k++) {
            float4 w = ((float4*)sW)[k * 16 + tx];
            #pragma unroll
            for (int i = 0; i < 4; i++) {
                float hv = sH[(ty * 4 + i) * HST + k];
                acc[i][0] += hv * w.x;
                acc[i][1] += hv * w.y;
                acc[i][2] += hv * w.z;
                acc[i][3] += hv * w.w;
            }
        }
        #pragma unroll
        for (int i = 0; i < 4; i++) {
            int row = n0 + ty * 4 + i;
            if (row < N_NODES)
                ((float4*)C)[row * 16 + tx] =
                    make_float4(acc[i][0], acc[i][1], acc[i][2], acc[i][3]);
        }
    }
}

// -------- the single persistent kernel --------
__global__ void __launch_bounds__(NT, 1)
k_mega(const float* __restrict__ embed,
       const float* __restrict__ W1s, const float* __restrict__ W1n, const float* __restrict__ b1,
       const float* __restrict__ W2s, const float* __restrict__ W2n, const float* __restrict__ b2,
       const float* __restrict__ Wfc, const float* __restrict__ bfc,
       const int* __restrict__ ids_w,
       const void* __restrict__ src, const void* __restrict__ dst,
       float* __restrict__ out) {
    extern __shared__ float sm[];
    int tid = threadIdx.x;
    int gt = blockIdx.x * NT + tid;

    // ---- phase 0: detect dtype, zero counters, embed -> fp16 table ----
    if (gt == 0) g_idx32 = (ids_w[2] == 2) ? 1 : 0;   // arange: int32 word[2]==2
    for (int i = gt; i < N_NODES; i += NTHREADS) { g_deg[i] = 0; g_fill[i] = 0; }
    for (int i = gt; i < N_NODES * 32; i += NTHREADS) {
        float2 v = ((const float2*)embed)[i];
        g_xh[i] = __floats2half2_rn(v.x, v.y);
    }
    grid_bar();

    // ---- phase 1: degree histogram + int32 stash ----
    for (int i = gt; i < N_EDGES; i += NTHREADS) {
        int d = read_idx(dst, i);
        int s = read_idx(src, i);
        g_dst32[i] = d;
        g_src32[i] = s;
        atomicAdd(&g_deg[d], 1);
    }
    grid_bar();

    // ---- phase 2: per-chunk inclusive scan (blocks 0..NCHUNK-1) ----
    if (blockIdx.x < NCHUNK) {
        __shared__ int wsum[16];
        int lane = tid & 31, wid = tid >> 5;
        int gid = blockIdx.x * SCAN_CH + tid;
        int x = (gid < N_NODES) ? g_deg[gid] : 0;
        #pragma unroll
        for (int off = 1; off < 32; off <<= 1) {
            int t = __shfl_up_sync(0xffffffff, x, off);
            if (lane >= off) x += t;
        }
        if (lane == 31) wsum[wid] = x;
        __syncthreads();
        if (wid == 0 && lane < 16) {
            int s = wsum[lane];
            #pragma unroll
            for (int off = 1; off < 16; off <<= 1) {
                int t = __shfl_up_sync(0x0000ffff, s, off);
                if (lane >= off) s += t;
            }
            wsum[lane] = s;
        }
        __syncthreads();
        if (wid > 0) x += wsum[wid - 1];
        if (gid < N_NODES) g_rowptr[gid + 1] = x;
        if (tid == SCAN_CH - 1) g_blocksum[blockIdx.x] = x;
        if (gid == 0) g_rowptr[0] = 0;
    }
    grid_bar();

    // ---- phase 3: scan the 98 blocksums (block 0) ----
    if (blockIdx.x == 0) {
        int* sh = (int*)sm;
        int v = (tid < NCHUNK) ? g_blocksum[tid] : 0;
        if (tid < 128) sh[tid] = v;
        __syncthreads();
        for (int off = 1; off < 128; off <<= 1) {
            int t = (tid < 128 && tid >= off) ? sh[tid - off] : 0;
            __syncthreads();
            if (tid < 128) sh[tid] += t;
            __syncthreads();
        }
        if (tid < NCHUNK) g_blockoff[tid] = sh[tid] - v;   // exclusive
    }
    grid_bar();

    // ---- phase 4: add chunk offsets ----
    if (blockIdx.x < NCHUNK) {
        int gid = blockIdx.x * SCAN_CH + tid;
        if (gid < N_NODES) g_rowptr[gid + 1] += g_blockoff[blockIdx.x];
    }
    grid_bar();

    // ---- phase 5: CSR fill ----
    for (int i = gt; i < N_EDGES; i += NTHREADS) {
        int d = g_dst32[i];
        int pos = g_rowptr[d] + atomicAdd(&g_fill[d], 1);
        g_col[pos] = g_src32[i];
    }
    grid_bar();

    // ---- phase 6: layer 1 (agg fp16 embed + transform, emits h1 + fp16 h1) ----
    phase_layer<true>(sm, g_xh, embed, W1s, W1n, b1, g_h1, g_h1h);
    grid_bar();

    // ---- phase 7: layer 2 ----
    phase_layer<false>(sm, g_h1h, g_h1, W2s, W2n, b2, g_h2, nullptr);
    grid_bar();

    // ---- phase 8: final linear ----
    phase_final(sm, g_h2, Wfc, bfc, out);
}

extern "C" void kernel_launch(void* const* d_in, const int* in_sizes, int n_in,
                              void* d_out, int out_size) {
    const float* embed   = (const float*)d_in[0];
    const float* W1_self = (const float*)d_in[1];
    const float* W1_neigh= (const float*)d_in[2];
    const float* b1      = (const float*)d_in[3];
    const float* W2_self = (const float*)d_in[4];
    const float* W2_neigh= (const float*)d_in[5];
    const float* b2      = (const float*)d_in[6];
    const float* W_fc    = (const float*)d_in[7];
    const float* b_fc    = (const float*)d_in[8];
    const int*   ids_w   = (const int*)d_in[9];
    const void*  src     = d_in[10];
    const void*  dst     = d_in[11];
    float* out = (float*)d_out;

    const int SMEM = (8192 + 2 * 128 * HST) * 4;   // 102400 B
    cudaFuncSetAttribute((const void*)k_mega,
                         cudaFuncAttributeMaxDynamicSharedMemorySize, SMEM);

    k_mega<<<NB, NT, SMEM>>>(embed, W1_self, W1_neigh, b1,
                             W2_self, W2_neigh, b2, W_fc, b_fc,
                             ids_w, src, dst, out);
}

// round 5
// speedup vs baseline: 1.7063x; 1.7063x over previous
#include <cuda_runtime.h>
#include <cstdint>

#define N_NODES 50000
#define FEATS   64
#define N_EDGES 800000
#define SCAN_B  1024
#define N_CHUNK ((N_NODES + SCAN_B - 1) / SCAN_B)   // 49
#define WST     72        // smem row stride (floats/words); B-frag conflict-free
#define NTILE   ((N_NODES + 127) >> 7)              // 391 tiles of 128 nodes

// -------- scratch (device globals; no allocation allowed) --------
__device__ int g_idx32;                 // 1 if indices are int32, 0 if int64
__device__ int g_deg[N_NODES];
__device__ int g_rowptr[N_NODES + 1];
__device__ int g_blocksum[64];
__device__ int g_blockoff[64];
__device__ int g_fill[N_NODES];
__device__ int g_col[N_EDGES];
__device__ __align__(16) float g_agg[N_NODES * FEATS];
__device__ __align__(16) float g_h1 [N_NODES * FEATS];
__device__ __align__(16) float g_h2 [N_NODES * FEATS];

// -------- dtype detection: item_ids == arange(N) --------
// int32 words: 0,1,2,... -> word[2]==2 ; int64 words: 0,0,1,0,2,0 -> word[2]==1
__global__ void k_detect(const int* ids_words) {
    g_idx32 = (ids_words[2] == 2) ? 1 : 0;
}

__global__ void k_zero() {
    int i = blockIdx.x * blockDim.x + threadIdx.x;
    if (i < N_NODES) { g_deg[i] = 0; g_fill[i] = 0; }
}

__device__ __forceinline__ int read_idx(const void* p, int i) {
    return g_idx32 ? ((const int*)p)[i] : (int)((const long long*)p)[i];
}

__global__ void k_degree(const void* __restrict__ dst) {
    int i = blockIdx.x * blockDim.x + threadIdx.x;
    if (i >= N_EDGES) return;
    atomicAdd(&g_deg[read_idx(dst, i)], 1);
}

// -------- 3-phase exclusive scan over g_deg -> g_rowptr (R1-proven) --------
__global__ void k_scan1() {
    __shared__ int sh[SCAN_B];
    int tid = threadIdx.x;
    int gid = blockIdx.x * SCAN_B + tid;
    int v = (gid < N_NODES) ? g_deg[gid] : 0;
    sh[tid] = v;
    __syncthreads();
    #pragma unroll
    for (int off = 1; off < SCAN_B; off <<= 1) {
        int t = (tid >= off) ? sh[tid - off] : 0;
        __syncthreads();
        sh[tid] += t;
        __syncthreads();
    }
    if (gid < N_NODES) g_rowptr[gid + 1] = sh[tid];
    if (tid == SCAN_B - 1) g_blocksum[blockIdx.x] = sh[tid];
    if (gid == 0) g_rowptr[0] = 0;
}

__global__ void k_scan2(int nb) {
    __shared__ int sh[64];
    int tid = threadIdx.x;
    int v = (tid < nb) ? g_blocksum[tid] : 0;
    sh[tid] = v;
    __syncthreads();
    #pragma unroll
    for (int off = 1; off < 64; off <<= 1) {
        int t = (tid >= off) ? sh[tid - off] : 0;
        __syncthreads();
        sh[tid] += t;
        __syncthreads();
    }
    g_blockoff[tid] = sh[tid] - v;   // exclusive
}

__global__ void k_scan3() {
    int gid = blockIdx.x * SCAN_B + threadIdx.x;
    if (gid < N_NODES) g_rowptr[gid + 1] += g_blockoff[blockIdx.x];
}

__global__ void k_fill(const void* __restrict__ src, const void* __restrict__ dst) {
    int i = blockIdx.x * blockDim.x + threadIdx.x;
    if (i >= N_EDGES) return;
    int d = read_idx(dst, i);
    int s = read_idx(src, i);
    int pos = g_rowptr[d] + atomicAdd(&g_fill[d], 1);
    g_col[pos] = s;
}

// -------- mean aggregation (R1-proven): one warp/node, lane owns 2 feats --------
__global__ void k_agg(const float* __restrict__ h, float* __restrict__ agg) {
    int warp = (blockIdx.x * blockDim.x + threadIdx.x) >> 5;
    int lane = threadIdx.x & 31;
    if (warp >= N_NODES) return;
    int s = g_rowptr[warp], e = g_rowptr[warp + 1];
    const float2* h2 = (const float2*)h;
    float2 a0 = make_float2(0.f, 0.f), a1 = make_float2(0.f, 0.f);
    int j = s;
    for (; j + 1 < e; j += 2) {
        int c0 = g_col[j], c1 = g_col[j + 1];
        float2 v0 = h2[c0 * 32 + lane];
        float2 v1 = h2[c1 * 32 + lane];
        a0.x += v0.x; a0.y += v0.y;
        a1.x += v1.x; a1.y += v1.y;
    }
    if (j < e) {
        int c = g_col[j];
        float2 v = h2[c * 32 + lane];
        a0.x += v.x; a0.y += v.y;
    }
    int deg = e - s;
    float inv = (deg > 0) ? (1.0f / (float)deg) : 0.0f;
    float2 o;
    o.x = (a0.x + a1.x) * inv;
    o.y = (a0.y + a1.y) * inv;
    ((float2*)agg)[warp * 32 + lane] = o;
}

// -------- tf32 tensor-core transform --------
__device__ __forceinline__ unsigned tf32cvt(float x) {
    unsigned r;
    asm("cvt.rna.tf32.f32 %0, %1;" : "=r"(r) : "f"(x));
    return r;
}

__device__ __forceinline__ void mma8(float* d,
                                     unsigned a0, unsigned a1, unsigned a2, unsigned a3,
                                     unsigned b0, unsigned b1) {
    asm volatile(
        "mma.sync.aligned.m16n8k8.row.col.f32.tf32.tf32.f32 "
        "{%0,%1,%2,%3}, {%4,%5,%6,%7}, {%8,%9}, {%0,%1,%2,%3};"
        : "+f"(d[0]), "+f"(d[1]), "+f"(d[2]), "+f"(d[3])
        : "r"(a0), "r"(a1), "r"(a2), "r"(a3), "r"(b0), "r"(b1));
}

// C = act(H@Ws [+ G@Wn] + b); tile = 128 nodes, 256 threads (8 warps x m16)
template <bool NEIGH, bool RELU>
__global__ void __launch_bounds__(256)
k_mma(const float* __restrict__ H, const float* __restrict__ G,
      const float* __restrict__ Ws, const float* __restrict__ Wn,
      const float* __restrict__ bias, float* __restrict__ C) {
    extern __shared__ unsigned sm[];
    unsigned* sWs = sm;                                     // 64*WST
    unsigned* sWn = NEIGH ? (sm + 64 * WST) : nullptr;      // 64*WST
    unsigned* sH  = NEIGH ? (sm + 2 * 64 * WST) : (sm + 64 * WST);  // 128*WST
    unsigned* sG  = NEIGH ? (sH + 128 * WST) : nullptr;     // 128*WST

    int tid = threadIdx.x;
    int lane = tid & 31, wid = tid >> 5;
    int n0node = blockIdx.x << 7;

    // stage weights (cvt to tf32 bits): 64 rows x 16 uint4
    for (int i = tid; i < 64 * 16; i += 256) {
        int r = i >> 4, c = i & 15;
        float4 v = ((const float4*)Ws)[i];
        ((uint4*)(sWs + r * WST))[c] =
            make_uint4(tf32cvt(v.x), tf32cvt(v.y), tf32cvt(v.z), tf32cvt(v.w));
        if (NEIGH) {
            float4 u = ((const float4*)Wn)[i];
            ((uint4*)(sWn + r * WST))[c] =
                make_uint4(tf32cvt(u.x), tf32cvt(u.y), tf32cvt(u.z), tf32cvt(u.w));
        }
    }
    // stage node tiles: 128 rows x 16 uint4 (guarded)
    for (int i = tid; i < 128 * 16; i += 256) {
        int r = i >> 4, c = i & 15;
        int gr = n0node + r;
        bool ok = (gr < N_NODES);
        float4 v = ok ? ((const float4*)H)[gr * 16 + c] : make_float4(0.f, 0.f, 0.f, 0.f);
        ((uint4*)(sH + r * WST))[c] =
            make_uint4(tf32cvt(v.x), tf32cvt(v.y), tf32cvt(v.z), tf32cvt(v.w));
        if (NEIGH) {
            float4 u = ok ? ((const float4*)G)[gr * 16 + c] : make_float4(0.f, 0.f, 0.f, 0.f);
            ((uint4*)(sG + r * WST))[c] =
                make_uint4(tf32cvt(u.x), tf32cvt(u.y), tf32cvt(u.z), tf32cvt(u.w));
        }
    }
    __syncthreads();

    int gID = lane >> 2;     // 0..7  (row-in-group / n-col)
    int tg  = lane & 3;      // 0..3  (col-in-group / k-row)
    int mb  = wid << 4;      // warp's 16-row base within the tile

    // accumulators: 8 n-tiles x {c0,c1,c2,c3}, init with bias
    float acc[8][4];
    #pragma unroll
    for (int n = 0; n < 8; n++) {
        float b0 = bias[n * 8 + tg * 2];
        float b1 = bias[n * 8 + tg * 2 + 1];
        acc[n][0] = b0; acc[n][1] = b1; acc[n][2] = b0; acc[n][3] = b1;
    }

    #pragma unroll
    for (int k0 = 0; k0 < 64; k0 += 8) {
        const unsigned* ah = sH + (mb + gID) * WST + k0 + tg;
        unsigned ha0 = ah[0], ha1 = ah[8 * WST], ha2 = ah[4], ha3 = ah[8 * WST + 4];
        unsigned ga0 = 0, ga1 = 0, ga2 = 0, ga3 = 0;
        if (NEIGH) {
            const unsigned* ag = sG + (mb + gID) * WST + k0 + tg;
            ga0 = ag[0]; ga1 = ag[8 * WST]; ga2 = ag[4]; ga3 = ag[8 * WST + 4];
        }
        #pragma unroll
        for (int n = 0; n < 8; n++) {
            const unsigned* bw = sWs + (k0 + tg) * WST + n * 8 + gID;
            mma8(acc[n], ha0, ha1, ha2, ha3, bw[0], bw[4 * WST]);
            if (NEIGH) {
                const unsigned* bn = sWn + (k0 + tg) * WST + n * 8 + gID;
                mma8(acc[n], ga0, ga1, ga2, ga3, bn[0], bn[4 * WST]);
            }
        }
    }

    // epilogue: c0,c1 -> (row gID, cols 2tg,2tg+1); c2,c3 -> row gID+8
    int r0 = n0node + mb + gID;
    int r1 = r0 + 8;
    #pragma unroll
    for (int n = 0; n < 8; n++) {
        int c = n * 8 + tg * 2;
        float2 v0, v1;
        v0.x = RELU ? fmaxf(acc[n][0], 0.f) : acc[n][0];
        v0.y = RELU ? fmaxf(acc[n][1], 0.f) : acc[n][1];
        v1.x = RELU ? fmaxf(acc[n][2], 0.f) : acc[n][2];
        v1.y = RELU ? fmaxf(acc[n][3], 0.f) : acc[n][3];
        if (r0 < N_NODES) *(float2*)(C + r0 * 64 + c) = v0;
        if (r1 < N_NODES) *(float2*)(C + r1 * 64 + c) = v1;
    }
}

extern "C" void kernel_launch(void* const* d_in, const int* in_sizes, int n_in,
                              void* d_out, int out_size) {
    const float* embed   = (const float*)d_in[0];
    const float* W1_self = (const float*)d_in[1];
    const float* W1_neigh= (const float*)d_in[2];
    const float* b1      = (const float*)d_in[3];
    const float* W2_self = (const float*)d_in[4];
    const float* W2_neigh= (const float*)d_in[5];
    const float* b2      = (const float*)d_in[6];
    const float* W_fc    = (const float*)d_in[7];
    const float* b_fc    = (const float*)d_in[8];
    const int*   ids_w   = (const int*)d_in[9];
    const void*  src     = d_in[10];
    const void*  dst     = d_in[11];
    float* out = (float*)d_out;

    const int SMEM_N = (2 * 64 * WST + 2 * 128 * WST) * 4;   // 110592 B
    const int SMEM_F = (64 * WST + 128 * WST) * 4;           // 55296 B
    cudaFuncSetAttribute((const void*)k_mma<true, true>,
                         cudaFuncAttributeMaxDynamicSharedMemorySize, SMEM_N);
    cudaFuncSetAttribute((const void*)k_mma<true, false>,
                         cudaFuncAttributeMaxDynamicSharedMemorySize, SMEM_N);
    cudaFuncSetAttribute((const void*)k_mma<false, false>,
                         cudaFuncAttributeMaxDynamicSharedMemorySize, SMEM_F);

    float* agg; cudaGetSymbolAddress((void**)&agg, g_agg);
    float* h1;  cudaGetSymbolAddress((void**)&h1,  g_h1);
    float* h2;  cudaGetSymbolAddress((void**)&h2,  g_h2);

    // --- CSR build (R1-proven) ---
    k_detect<<<1, 1>>>(ids_w);
    k_zero<<<(N_NODES + 255) / 256, 256>>>();
    k_degree<<<(N_EDGES + 255) / 256, 256>>>(dst);
    k_scan1<<<N_CHUNK, SCAN_B>>>();
    k_scan2<<<1, 64>>>(N_CHUNK);
    k_scan3<<<N_CHUNK, SCAN_B>>>();
    k_fill<<<(N_EDGES + 255) / 256, 256>>>(src, dst);

    const int AGG_BLOCKS = (N_NODES * 32 + 255) / 256;

    // --- Layer 1 ---
    k_agg<<<AGG_BLOCKS, 256>>>(embed, agg);
    k_mma<true, true><<<NTILE, 256, SMEM_N>>>(embed, agg, W1_self, W1_neigh, b1, h1);

    // --- Layer 2 ---
    k_agg<<<AGG_BLOCKS, 256>>>(h1, agg);
    k_mma<true, false><<<NTILE, 256, SMEM_N>>>(h1, agg, W2_self, W2_neigh, b2, h2);

    // --- Final linear ---
    k_mma<false, false><<<NTILE, 256, SMEM_F>>>(h2, nullptr, W_fc, nullptr, b_fc, out);
}